// round 8
// baseline (speedup 1.0000x reference)
#include <cuda_runtime.h>
#include <cuda_bf16.h>
#include <cstdint>

// ---------------------------------------------------------------------------
// LSTM_41764261986630 : 2-layer LSTM, T=512, B=64, IN=H=512
// mma.sync (HMMA) bf16 3-term split, persistent, weight-stationary.
// R7: split accumulators (hi*hi vs corrections) to break HMMA RAW chains;
//     one __syncthreads per chunk (wait -> sync -> prefetch -> compute).
// ---------------------------------------------------------------------------

#define TSTEPS 512
#define BATCH  64
#define HID    512
#define BH     (BATCH*HID)
#define NCTA   128
#define NTHR   128

// SMEM byte offsets
#define SO_W    0          // 131072 B : [plane][tile 0..127][256 bf16]
#define SO_A    131072     // 2 stages x (2 planes x 16384 B)
#define SO_BIAS 196608     // 32 floats
#define SMEM_TOTAL 196736

// ---- persistent device scratch (no cudaMalloc allowed) ----
__device__ __align__(16) __nv_bfloat16 g_w[(size_t)NCTA*2*128*256];      // 16MB
__device__ __align__(16) __nv_bfloat16 g_x_hi[(size_t)TSTEPS*32768];     // 32MB
__device__ __align__(16) __nv_bfloat16 g_x_lo[(size_t)TSTEPS*32768];     // 32MB
__device__ __align__(16) __nv_bfloat16 g_h0_hi[2*32768], g_h0_lo[2*32768];
__device__ __align__(16) __nv_bfloat16 g_h1_hi[2*32768], g_h1_lo[2*32768];
__device__ unsigned g_bar;

// ---------------- helpers ----------------
__device__ __forceinline__ void cp_async16(void* sdst, const void* gsrc) {
    unsigned sa;
    asm("{ .reg .u64 t; cvta.to.shared.u64 t, %1; cvt.u32.u64 %0, t; }"
        : "=r"(sa) : "l"(sdst));
    asm volatile("cp.async.cg.shared.global [%0], [%1], 16;\n" :: "r"(sa), "l"(gsrc));
}
#define CP_COMMIT() asm volatile("cp.async.commit_group;\n")
#define CP_WAIT(n)  asm volatile("cp.async.wait_group %0;\n" :: "n"(n))

__device__ __forceinline__ void mma16816(float* d,
        uint32_t a0, uint32_t a1, uint32_t a2, uint32_t a3,
        uint32_t b0, uint32_t b1) {
    asm volatile(
      "mma.sync.aligned.m16n8k16.row.col.f32.bf16.bf16.f32 "
      "{%0,%1,%2,%3}, {%4,%5,%6,%7}, {%8,%9}, {%0,%1,%2,%3};"
      : "+f"(d[0]), "+f"(d[1]), "+f"(d[2]), "+f"(d[3])
      : "r"(a0), "r"(a1), "r"(a2), "r"(a3), "r"(b0), "r"(b1));
}

// fragment-order position of k-local element within a 16-wide act row
__device__ __host__ __forceinline__ int p_of_kl(int kl) {
    return ((kl & 7) >> 1) * 4 + ((kl >> 3) << 1) + (kl & 1);
}

// grid barrier (monotonic counter: safe across graph replays)
__device__ __forceinline__ void grid_sync() {
    __threadfence();
    __syncthreads();
    if (threadIdx.x == 0) {
        unsigned arrive = atomicAdd(&g_bar, 1u);
        unsigned target = (arrive / NCTA + 1u) * NCTA;
        while (*(volatile unsigned*)&g_bar < target) { }
        __threadfence();
    }
    __syncthreads();
}

// ---------------- prep kernels ----------------
// W fragment image per CTA: [plane hi/lo][tile ti = s*2+mb][lane L][8 bf16]
__global__ void prep_w(const float* __restrict__ Wx, const float* __restrict__ Wh) {
    const int blk = blockIdx.x;               // cta*8 + ch
    const int ch = blk & 7, cta = blk >> 3;
    const int layer = cta >> 6, hb = cta & 63;
    const float* wx = Wx + (size_t)layer * 2048 * 512;
    const float* wh = Wh + (size_t)layer * 2048 * 512;
    const size_t base_hi = ((size_t)cta * 2 + 0) * 128 * 256;
    const size_t base_lo = ((size_t)cta * 2 + 1) * 128 * 256;
    for (int e = threadIdx.x; e < 16 * 256; e += blockDim.x) {
        int ti  = ch * 16 + (e >> 8);
        int q16 = e & 255;
        int L = q16 >> 3, eb = q16 & 7;
        int qreg = eb >> 1, half = eb & 1;
        int s = ti >> 1, mb = ti & 1;
        int m  = (L >> 2) + ((qreg & 1) << 3) + (mb << 4);   // row 0..31
        int kl = ((L & 3) << 1) + ((qreg >> 1) << 3) + half;
        int k  = (s << 4) + kl;
        int R  = (m >> 3) * 512 + hb * 8 + (m & 7);
        float v = (k < 512) ? wx[(size_t)R * 512 + k]
                            : wh[(size_t)R * 512 + (k - 512)];
        __nv_bfloat16 hi = __float2bfloat16(v);
        __nv_bfloat16 lo = __float2bfloat16(v - __bfloat162float(hi));
        size_t off = (size_t)ti * 256 + q16;
        g_w[base_hi + off] = hi;
        g_w[base_lo + off] = lo;
    }
}

// x fragment image: [t][s 0..31][n 0..63][16], k-local position p = p_of_kl(kl)
__global__ void prep_x(const float* __restrict__ x) {
    const int t = blockIdx.x;
    const float* src = x + (size_t)t * BH;
    const size_t dst = (size_t)t * 32768;
    for (int e = threadIdx.x; e < 32768; e += blockDim.x) {
        int s = e >> 10, n = (e >> 4) & 63, p = e & 15;
        int q = p >> 2, r = p & 3;
        int kl = (q << 1) + (r & 1) + ((r >> 1) << 3);
        float v = src[n * 512 + ((s << 4) + kl)];
        __nv_bfloat16 hi = __float2bfloat16(v);
        __nv_bfloat16 lo = __float2bfloat16(v - __bfloat162float(hi));
        g_x_hi[dst + e] = hi;
        g_x_lo[dst + e] = lo;
    }
}

// ---------------- main persistent kernel ----------------
__global__ void __launch_bounds__(NTHR, 1)
lstm_mma(const float* __restrict__ bh, float* __restrict__ out)
{
    extern __shared__ __align__(16) char smem[];
    const int tid = threadIdx.x;
    const int L = tid & 31, warp = tid >> 5;
    const int cta = blockIdx.x, layer = cta >> 6, hb = cta & 63;

    // ---- resident weight load (once) ----
    {
        const char* wsrc = (const char*)(g_w + (size_t)cta * 65536);
        for (int i = tid; i < 8192; i += NTHR)
            cp_async16(smem + SO_W + i * 16, wsrc + i * 16);
        CP_COMMIT();
    }
    float* bias_s = (float*)(smem + SO_BIAS);
    if (tid < 32)
        bias_s[tid] = bh[layer * 2048 + (tid >> 3) * 512 + hb * 8 + (tid & 7)];
    CP_WAIT(0);
    __syncthreads();

    // epilogue constants
    const int j  = L >> 2;                 // hidden within CTA (0..7)
    const int hh = hb * 8 + j;             // global hidden index
    const int sH = hh >> 4;
    const int pH = p_of_kl(hh & 15);
    const float bi = bias_s[j],      bf = bias_s[8 + j];
    const float bg = bias_s[16 + j], bo = bias_s[24 + j];

    float c_st[4] = {0.f, 0.f, 0.f, 0.f};
    float h_st[4] = {0.f, 0.f, 0.f, 0.f};

    const int n0 = (warp << 4) + (L >> 2);   // act row for nb=0
    const char* wbase = smem + SO_W;

    for (int w = 0; w <= TSTEPS; ++w) {
        const bool active = (layer == 0) ? (w < TSTEPS) : (w >= 1);
        if (active) {
            const int t = (layer == 0) ? w : (w - 1);
            const int nch = (t == 0) ? 4 : 8;

            const __nv_bfloat16 *Ahi, *Alo, *Bhi, *Blo;
            if (layer == 0) {
                Ahi = g_x_hi + (size_t)t * 32768;  Alo = g_x_lo + (size_t)t * 32768;
                Bhi = g_h0_hi + ((t - 1) & 1) * 32768;
                Blo = g_h0_lo + ((t - 1) & 1) * 32768;
            } else {
                Ahi = g_h0_hi + (t & 1) * 32768;   Alo = g_h0_lo + (t & 1) * 32768;
                Bhi = g_h1_hi + ((t - 1) & 1) * 32768;
                Blo = g_h1_lo + ((t - 1) & 1) * 32768;
            }

            // split accumulators: d = hi*hi chains, dc = correction chains
            float d[2][2][4], dc[2][2][4];
            #pragma unroll
            for (int mb = 0; mb < 2; ++mb)
                #pragma unroll
                for (int nb = 0; nb < 2; ++nb)
                    #pragma unroll
                    for (int q = 0; q < 4; ++q) { d[mb][nb][q] = 0.f; dc[mb][nb][q] = 0.f; }

            auto prefetch = [&](int c) {
                const int st = c & 1;
                const __nv_bfloat16* shi = (c < 4) ? Ahi + c * 8192 : Bhi + (c - 4) * 8192;
                const __nv_bfloat16* slo = (c < 4) ? Alo + c * 8192 : Blo + (c - 4) * 8192;
                char* dhi = smem + SO_A + st * 32768;
                char* dlo = dhi + 16384;
                #pragma unroll
                for (int i = 0; i < 8; ++i) {
                    int e = i * NTHR + tid;
                    cp_async16(dhi + e * 16, (const char*)shi + e * 16);
                    cp_async16(dlo + e * 16, (const char*)slo + e * 16);
                }
                CP_COMMIT();
            };

            prefetch(0);
            for (int c = 0; c < nch; ++c) {
                CP_WAIT(0);          // single in-flight group: chunk c landed
                __syncthreads();     // publishes chunk c; also protects stage (c+1)&1
                if (c + 1 < nch) prefetch(c + 1);

                const char* ahi = smem + SO_A + (c & 1) * 32768;
                const char* alo = ahi + 16384;
                #pragma unroll
                for (int sl = 0; sl < 8; ++sl) {
                    const int s2 = ((c << 3) + sl) << 1;   // tile = s*2 (+mb)
                    uint4 wh0 = *(const uint4*)(wbase + (size_t)(      s2    ) * 512 + L * 16);
                    uint4 wh1 = *(const uint4*)(wbase + (size_t)(      s2 + 1) * 512 + L * 16);
                    uint4 wl0 = *(const uint4*)(wbase + (size_t)(128 + s2    ) * 512 + L * 16);
                    uint4 wl1 = *(const uint4*)(wbase + (size_t)(128 + s2 + 1) * 512 + L * 16);
                    const int ro0 = ((sl << 6) + n0) * 32 + (L & 3) * 8;
                    const int ro1 = ro0 + 8 * 32;
                    uint2 ah0 = *(const uint2*)(ahi + ro0);
                    uint2 ah1 = *(const uint2*)(ahi + ro1);
                    uint2 al0 = *(const uint2*)(alo + ro0);
                    uint2 al1 = *(const uint2*)(alo + ro1);

                    // hi*hi into d (4 independent chains)
                    mma16816(d[0][0], wh0.x, wh0.y, wh0.z, wh0.w, ah0.x, ah0.y);
                    mma16816(d[0][1], wh0.x, wh0.y, wh0.z, wh0.w, ah1.x, ah1.y);
                    mma16816(d[1][0], wh1.x, wh1.y, wh1.z, wh1.w, ah0.x, ah0.y);
                    mma16816(d[1][1], wh1.x, wh1.y, wh1.z, wh1.w, ah1.x, ah1.y);
                    // corrections into dc (4 more chains; same-chain distance 4)
                    mma16816(dc[0][0], wh0.x, wh0.y, wh0.z, wh0.w, al0.x, al0.y);
                    mma16816(dc[0][1], wh0.x, wh0.y, wh0.z, wh0.w, al1.x, al1.y);
                    mma16816(dc[1][0], wh1.x, wh1.y, wh1.z, wh1.w, al0.x, al0.y);
                    mma16816(dc[1][1], wh1.x, wh1.y, wh1.z, wh1.w, al1.x, al1.y);
                    mma16816(dc[0][0], wl0.x, wl0.y, wl0.z, wl0.w, ah0.x, ah0.y);
                    mma16816(dc[0][1], wl0.x, wl0.y, wl0.z, wl0.w, ah1.x, ah1.y);
                    mma16816(dc[1][0], wl1.x, wl1.y, wl1.z, wl1.w, ah0.x, ah0.y);
                    mma16816(dc[1][1], wl1.x, wl1.y, wl1.z, wl1.w, ah1.x, ah1.y);
                }
            }

            // ---- epilogue: merge accumulators; gates; republish h ----
            __nv_bfloat16* dh_hi = (layer ? g_h1_hi : g_h0_hi) + (t & 1) * 32768;
            __nv_bfloat16* dh_lo = (layer ? g_h1_lo : g_h0_lo) + (t & 1) * 32768;
            float* orow = out + (size_t)t * BH;
            #pragma unroll
            for (int nb = 0; nb < 2; ++nb) {
                #pragma unroll
                for (int cc = 0; cc < 2; ++cc) {
                    const int si = nb * 2 + cc;
                    const int b  = (warp << 4) + (nb << 3) + ((L & 3) << 1) + cc;
                    float pi = d[0][nb][cc]     + dc[0][nb][cc]     + bi;
                    float pf = d[0][nb][2 + cc] + dc[0][nb][2 + cc] + bf;
                    float pg = d[1][nb][cc]     + dc[1][nb][cc]     + bg;
                    float po = d[1][nb][2 + cc] + dc[1][nb][2 + cc] + bo;
                    float ig = __fdividef(1.f, 1.f + __expf(-pi));
                    float fg = __fdividef(1.f, 1.f + __expf(-pf));
                    float gt = 2.f * __fdividef(1.f, 1.f + __expf(-2.f * pg)) - 1.f;
                    float og = __fdividef(1.f, 1.f + __expf(-po));
                    float cn = fg * c_st[si] + ig * gt;
                    c_st[si] = cn;
                    float th = 2.f * __fdividef(1.f, 1.f + __expf(-2.f * cn)) - 1.f;
                    float hn = og * th;
                    h_st[si] = hn;
                    __nv_bfloat16 hhi = __float2bfloat16(hn);
                    __nv_bfloat16 hlo = __float2bfloat16(hn - __bfloat162float(hhi));
                    const int idx = sH * 1024 + b * 16 + pH;
                    dh_hi[idx] = hhi;
                    dh_lo[idx] = hlo;
                    if (layer == 1) orow[b * 512 + hh] = hn;
                }
            }
        }
        grid_sync();
    }

    // ---- final h, c tails: out layout = [out | h(L,B,H) | c(L,B,H)] ----
    const size_t base = (size_t)TSTEPS * BH;
    #pragma unroll
    for (int nb = 0; nb < 2; ++nb)
        #pragma unroll
        for (int cc = 0; cc < 2; ++cc) {
            const int si = nb * 2 + cc;
            const int b  = (warp << 4) + (nb << 3) + ((L & 3) << 1) + cc;
            out[base + (size_t)layer * BH + (size_t)b * 512 + hh] = h_st[si];
            out[base + 2 * (size_t)BH + (size_t)layer * BH + (size_t)b * 512 + hh] = c_st[si];
        }
}

extern "C" void kernel_launch(void* const* d_in, const int* in_sizes, int n_in,
                              void* d_out, int out_size) {
    (void)in_sizes; (void)n_in; (void)out_size;
    const float* x  = (const float*)d_in[0];
    const float* Wx = (const float*)d_in[1];
    const float* Wh = (const float*)d_in[2];
    const float* bh = (const float*)d_in[3];
    float* out = (float*)d_out;

    prep_w<<<NCTA * 8, 128>>>(Wx, Wh);
    prep_x<<<TSTEPS, 256>>>(x);

    cudaFuncSetAttribute(lstm_mma, cudaFuncAttributeMaxDynamicSharedMemorySize,
                         SMEM_TOTAL);
    lstm_mma<<<NCTA, NTHR, SMEM_TOTAL>>>(bh, out);
}

// round 9
// speedup vs baseline: 1.1215x; 1.1215x over previous
#include <cuda_runtime.h>
#include <cuda_bf16.h>
#include <cstdint>

// ---------------------------------------------------------------------------
// LSTM_41764261986630 : 2-layer LSTM, T=512, B=64, IN=H=512
// mma.sync (HMMA) bf16 3-term split, persistent, weight-stationary.
// R8 = R6 skeleton + (1) MMA chain interleave (acc reuse distance 1 -> 4)
//               + (2) register double-buffer of fragments one sl ahead.
// ---------------------------------------------------------------------------

#define TSTEPS 512
#define BATCH  64
#define HID    512
#define BH     (BATCH*HID)
#define NCTA   128
#define NTHR   128

// SMEM byte offsets
#define SO_W    0          // 131072 B : [plane][tile 0..127][256 bf16]
#define SO_A    131072     // 2 stages x (2 planes x 16384 B)
#define SO_BIAS 196608     // 32 floats
#define SMEM_TOTAL 196736

// ---- persistent device scratch (no cudaMalloc allowed) ----
__device__ __align__(16) __nv_bfloat16 g_w[(size_t)NCTA*2*128*256];      // 16MB
__device__ __align__(16) __nv_bfloat16 g_x_hi[(size_t)TSTEPS*32768];     // 32MB
__device__ __align__(16) __nv_bfloat16 g_x_lo[(size_t)TSTEPS*32768];     // 32MB
__device__ __align__(16) __nv_bfloat16 g_h0_hi[2*32768], g_h0_lo[2*32768];
__device__ __align__(16) __nv_bfloat16 g_h1_hi[2*32768], g_h1_lo[2*32768];
__device__ unsigned g_bar;

// ---------------- helpers ----------------
__device__ __forceinline__ void cp_async16(void* sdst, const void* gsrc) {
    unsigned sa;
    asm("{ .reg .u64 t; cvta.to.shared.u64 t, %1; cvt.u32.u64 %0, t; }"
        : "=r"(sa) : "l"(sdst));
    asm volatile("cp.async.cg.shared.global [%0], [%1], 16;\n" :: "r"(sa), "l"(gsrc));
}
#define CP_COMMIT() asm volatile("cp.async.commit_group;\n")
#define CP_WAIT(n)  asm volatile("cp.async.wait_group %0;\n" :: "n"(n))

__device__ __forceinline__ void mma16816(float* d,
        uint32_t a0, uint32_t a1, uint32_t a2, uint32_t a3,
        uint32_t b0, uint32_t b1) {
    asm volatile(
      "mma.sync.aligned.m16n8k16.row.col.f32.bf16.bf16.f32 "
      "{%0,%1,%2,%3}, {%4,%5,%6,%7}, {%8,%9}, {%0,%1,%2,%3};"
      : "+f"(d[0]), "+f"(d[1]), "+f"(d[2]), "+f"(d[3])
      : "r"(a0), "r"(a1), "r"(a2), "r"(a3), "r"(b0), "r"(b1));
}

// fragment-order position of k-local element within a 16-wide act row
__device__ __host__ __forceinline__ int p_of_kl(int kl) {
    return ((kl & 7) >> 1) * 4 + ((kl >> 3) << 1) + (kl & 1);
}

// grid barrier (monotonic counter: safe across graph replays)
__device__ __forceinline__ void grid_sync() {
    __threadfence();
    __syncthreads();
    if (threadIdx.x == 0) {
        unsigned arrive = atomicAdd(&g_bar, 1u);
        unsigned target = (arrive / NCTA + 1u) * NCTA;
        while (*(volatile unsigned*)&g_bar < target) { }
        __threadfence();
    }
    __syncthreads();
}

// ---------------- prep kernels ----------------
// W fragment image per CTA: [plane hi/lo][tile ti = s*2+mb][lane L][8 bf16]
__global__ void prep_w(const float* __restrict__ Wx, const float* __restrict__ Wh) {
    const int blk = blockIdx.x;               // cta*8 + ch
    const int ch = blk & 7, cta = blk >> 3;
    const int layer = cta >> 6, hb = cta & 63;
    const float* wx = Wx + (size_t)layer * 2048 * 512;
    const float* wh = Wh + (size_t)layer * 2048 * 512;
    const size_t base_hi = ((size_t)cta * 2 + 0) * 128 * 256;
    const size_t base_lo = ((size_t)cta * 2 + 1) * 128 * 256;
    for (int e = threadIdx.x; e < 16 * 256; e += blockDim.x) {
        int ti  = ch * 16 + (e >> 8);
        int q16 = e & 255;
        int L = q16 >> 3, eb = q16 & 7;
        int qreg = eb >> 1, half = eb & 1;
        int s = ti >> 1, mb = ti & 1;
        int m  = (L >> 2) + ((qreg & 1) << 3) + (mb << 4);   // row 0..31
        int kl = ((L & 3) << 1) + ((qreg >> 1) << 3) + half;
        int k  = (s << 4) + kl;
        int R  = (m >> 3) * 512 + hb * 8 + (m & 7);
        float v = (k < 512) ? wx[(size_t)R * 512 + k]
                            : wh[(size_t)R * 512 + (k - 512)];
        __nv_bfloat16 hi = __float2bfloat16(v);
        __nv_bfloat16 lo = __float2bfloat16(v - __bfloat162float(hi));
        size_t off = (size_t)ti * 256 + q16;
        g_w[base_hi + off] = hi;
        g_w[base_lo + off] = lo;
    }
}

// x fragment image: [t][s 0..31][n 0..63][16], k-local position p = p_of_kl(kl)
__global__ void prep_x(const float* __restrict__ x) {
    const int t = blockIdx.x;
    const float* src = x + (size_t)t * BH;
    const size_t dst = (size_t)t * 32768;
    for (int e = threadIdx.x; e < 32768; e += blockDim.x) {
        int s = e >> 10, n = (e >> 4) & 63, p = e & 15;
        int q = p >> 2, r = p & 3;
        int kl = (q << 1) + (r & 1) + ((r >> 1) << 3);
        float v = src[n * 512 + ((s << 4) + kl)];
        __nv_bfloat16 hi = __float2bfloat16(v);
        __nv_bfloat16 lo = __float2bfloat16(v - __bfloat162float(hi));
        g_x_hi[dst + e] = hi;
        g_x_lo[dst + e] = lo;
    }
}

// ---------------- main persistent kernel ----------------
__global__ void __launch_bounds__(NTHR, 1)
lstm_mma(const float* __restrict__ bh, float* __restrict__ out)
{
    extern __shared__ __align__(16) char smem[];
    const int tid = threadIdx.x;
    const int L = tid & 31, warp = tid >> 5;
    const int cta = blockIdx.x, layer = cta >> 6, hb = cta & 63;

    // ---- resident weight load (once) ----
    {
        const char* wsrc = (const char*)(g_w + (size_t)cta * 65536);
        for (int i = tid; i < 8192; i += NTHR)
            cp_async16(smem + SO_W + i * 16, wsrc + i * 16);
        CP_COMMIT();
    }
    float* bias_s = (float*)(smem + SO_BIAS);
    if (tid < 32)
        bias_s[tid] = bh[layer * 2048 + (tid >> 3) * 512 + hb * 8 + (tid & 7)];
    CP_WAIT(0);
    __syncthreads();

    // epilogue constants
    const int j  = L >> 2;                 // hidden within CTA (0..7)
    const int hh = hb * 8 + j;             // global hidden index
    const int sH = hh >> 4;
    const int pH = p_of_kl(hh & 15);
    const float bi = bias_s[j],      bf = bias_s[8 + j];
    const float bg = bias_s[16 + j], bo = bias_s[24 + j];

    float c_st[4] = {0.f, 0.f, 0.f, 0.f};
    float h_st[4] = {0.f, 0.f, 0.f, 0.f};

    const int n0 = (warp << 4) + (L >> 2);   // act row for nb=0
    const char* wbase = smem + SO_W;

    for (int w = 0; w <= TSTEPS; ++w) {
        const bool active = (layer == 0) ? (w < TSTEPS) : (w >= 1);
        if (active) {
            const int t = (layer == 0) ? w : (w - 1);
            const int nch = (t == 0) ? 4 : 8;

            const __nv_bfloat16 *Ahi, *Alo, *Bhi, *Blo;
            if (layer == 0) {
                Ahi = g_x_hi + (size_t)t * 32768;  Alo = g_x_lo + (size_t)t * 32768;
                Bhi = g_h0_hi + ((t - 1) & 1) * 32768;
                Blo = g_h0_lo + ((t - 1) & 1) * 32768;
            } else {
                Ahi = g_h0_hi + (t & 1) * 32768;   Alo = g_h0_lo + (t & 1) * 32768;
                Bhi = g_h1_hi + ((t - 1) & 1) * 32768;
                Blo = g_h1_lo + ((t - 1) & 1) * 32768;
            }

            float d[2][2][4];
            #pragma unroll
            for (int mb = 0; mb < 2; ++mb)
                #pragma unroll
                for (int nb = 0; nb < 2; ++nb)
                    #pragma unroll
                    for (int q = 0; q < 4; ++q) d[mb][nb][q] = 0.f;

            auto prefetch = [&](int c) {
                const int st = c & 1;
                const __nv_bfloat16* shi = (c < 4) ? Ahi + c * 8192 : Bhi + (c - 4) * 8192;
                const __nv_bfloat16* slo = (c < 4) ? Alo + c * 8192 : Blo + (c - 4) * 8192;
                char* dhi = smem + SO_A + st * 32768;
                char* dlo = dhi + 16384;
                #pragma unroll
                for (int i = 0; i < 8; ++i) {
                    int e = i * NTHR + tid;
                    cp_async16(dhi + e * 16, (const char*)shi + e * 16);
                    cp_async16(dlo + e * 16, (const char*)slo + e * 16);
                }
                CP_COMMIT();
            };

            prefetch(0);
            for (int c = 0; c < nch; ++c) {
                if (c + 1 < nch) { prefetch(c + 1); CP_WAIT(1); }
                else             { CP_WAIT(0); }
                __syncthreads();

                const char* ahi = smem + SO_A + (c & 1) * 32768;
                const char* alo = ahi + 16384;

                // fragment double buffer (one sl ahead)
                uint4 WH0[2], WH1[2], WL0[2], WL1[2];
                uint2 AH0[2], AH1[2], AL0[2], AL1[2];

                auto ldfrag = [&](int sl, int bufi) {
                    const int s2 = ((c << 3) + sl) << 1;
                    WH0[bufi] = *(const uint4*)(wbase + (size_t)(      s2    ) * 512 + L * 16);
                    WH1[bufi] = *(const uint4*)(wbase + (size_t)(      s2 + 1) * 512 + L * 16);
                    WL0[bufi] = *(const uint4*)(wbase + (size_t)(128 + s2    ) * 512 + L * 16);
                    WL1[bufi] = *(const uint4*)(wbase + (size_t)(128 + s2 + 1) * 512 + L * 16);
                    const int ro0 = ((sl << 6) + n0) * 32 + (L & 3) * 8;
                    const int ro1 = ro0 + 8 * 32;
                    AH0[bufi] = *(const uint2*)(ahi + ro0);
                    AH1[bufi] = *(const uint2*)(ahi + ro1);
                    AL0[bufi] = *(const uint2*)(alo + ro0);
                    AL1[bufi] = *(const uint2*)(alo + ro1);
                };

                ldfrag(0, 0);
                #pragma unroll
                for (int sl = 0; sl < 8; ++sl) {
                    const int cur = sl & 1;
                    if (sl < 7) ldfrag(sl + 1, cur ^ 1);

                    const uint4 wh0 = WH0[cur], wh1 = WH1[cur];
                    const uint4 wl0 = WL0[cur], wl1 = WL1[cur];
                    const uint2 ah0 = AH0[cur], ah1 = AH1[cur];
                    const uint2 al0 = AL0[cur], al1 = AL1[cur];

                    // interleaved: same-accumulator reuse distance = 4
                    mma16816(d[0][0], wh0.x, wh0.y, wh0.z, wh0.w, ah0.x, ah0.y);
                    mma16816(d[0][1], wh0.x, wh0.y, wh0.z, wh0.w, ah1.x, ah1.y);
                    mma16816(d[1][0], wh1.x, wh1.y, wh1.z, wh1.w, ah0.x, ah0.y);
                    mma16816(d[1][1], wh1.x, wh1.y, wh1.z, wh1.w, ah1.x, ah1.y);

                    mma16816(d[0][0], wh0.x, wh0.y, wh0.z, wh0.w, al0.x, al0.y);
                    mma16816(d[0][1], wh0.x, wh0.y, wh0.z, wh0.w, al1.x, al1.y);
                    mma16816(d[1][0], wh1.x, wh1.y, wh1.z, wh1.w, al0.x, al0.y);
                    mma16816(d[1][1], wh1.x, wh1.y, wh1.z, wh1.w, al1.x, al1.y);

                    mma16816(d[0][0], wl0.x, wl0.y, wl0.z, wl0.w, ah0.x, ah0.y);
                    mma16816(d[0][1], wl0.x, wl0.y, wl0.z, wl0.w, ah1.x, ah1.y);
                    mma16816(d[1][0], wl1.x, wl1.y, wl1.z, wl1.w, ah0.x, ah0.y);
                    mma16816(d[1][1], wl1.x, wl1.y, wl1.z, wl1.w, ah1.x, ah1.y);
                }
                __syncthreads();
            }

            // ---- epilogue: gates; republish h (frag order) ----
            __nv_bfloat16* dh_hi = (layer ? g_h1_hi : g_h0_hi) + (t & 1) * 32768;
            __nv_bfloat16* dh_lo = (layer ? g_h1_lo : g_h0_lo) + (t & 1) * 32768;
            float* orow = out + (size_t)t * BH;
            #pragma unroll
            for (int nb = 0; nb < 2; ++nb) {
                #pragma unroll
                for (int cc = 0; cc < 2; ++cc) {
                    const int si = nb * 2 + cc;
                    const int b  = (warp << 4) + (nb << 3) + ((L & 3) << 1) + cc;
                    float pi = d[0][nb][cc]     + bi;
                    float pf = d[0][nb][2 + cc] + bf;
                    float pg = d[1][nb][cc]     + bg;
                    float po = d[1][nb][2 + cc] + bo;
                    float ig = __fdividef(1.f, 1.f + __expf(-pi));
                    float fg = __fdividef(1.f, 1.f + __expf(-pf));
                    float gt = 2.f * __fdividef(1.f, 1.f + __expf(-2.f * pg)) - 1.f;
                    float og = __fdividef(1.f, 1.f + __expf(-po));
                    float cn = fg * c_st[si] + ig * gt;
                    c_st[si] = cn;
                    float th = 2.f * __fdividef(1.f, 1.f + __expf(-2.f * cn)) - 1.f;
                    float hn = og * th;
                    h_st[si] = hn;
                    __nv_bfloat16 hhi = __float2bfloat16(hn);
                    __nv_bfloat16 hlo = __float2bfloat16(hn - __bfloat162float(hhi));
                    const int idx = sH * 1024 + b * 16 + pH;
                    dh_hi[idx] = hhi;
                    dh_lo[idx] = hlo;
                    if (layer == 1) orow[b * 512 + hh] = hn;
                }
            }
        }
        grid_sync();
    }

    // ---- final h, c tails: out layout = [out | h(L,B,H) | c(L,B,H)] ----
    const size_t base = (size_t)TSTEPS * BH;
    #pragma unroll
    for (int nb = 0; nb < 2; ++nb)
        #pragma unroll
        for (int cc = 0; cc < 2; ++cc) {
            const int si = nb * 2 + cc;
            const int b  = (warp << 4) + (nb << 3) + ((L & 3) << 1) + cc;
            out[base + (size_t)layer * BH + (size_t)b * 512 + hh] = h_st[si];
            out[base + 2 * (size_t)BH + (size_t)layer * BH + (size_t)b * 512 + hh] = c_st[si];
        }
}

extern "C" void kernel_launch(void* const* d_in, const int* in_sizes, int n_in,
                              void* d_out, int out_size) {
    (void)in_sizes; (void)n_in; (void)out_size;
    const float* x  = (const float*)d_in[0];
    const float* Wx = (const float*)d_in[1];
    const float* Wh = (const float*)d_in[2];
    const float* bh = (const float*)d_in[3];
    float* out = (float*)d_out;

    prep_w<<<NCTA * 8, 128>>>(Wx, Wh);
    prep_x<<<TSTEPS, 256>>>(x);

    cudaFuncSetAttribute(lstm_mma, cudaFuncAttributeMaxDynamicSharedMemorySize,
                         SMEM_TOTAL);
    lstm_mma<<<NCTA, NTHR, SMEM_TOTAL>>>(bh, out);
}

// round 10
// speedup vs baseline: 1.3453x; 1.1995x over previous
#include <cuda_runtime.h>
#include <cuda_fp16.h>
#include <cstdint>

// ---------------------------------------------------------------------------
// LSTM_41764261986630 : 2-layer LSTM, T=512, B=64, IN=H=512
// mma.sync (HMMA) fp16 2-term split (Whi*A + Wlo*A), persistent,
// weight-stationary.  R9: 768 -> 512 MMAs/warp/wave (legacy-HMMA rate-bound).
// Skeleton identical to R8 (fragment layouts, double-buffer, interleave).
// ---------------------------------------------------------------------------

#define TSTEPS 512
#define BATCH  64
#define HID    512
#define BH     (BATCH*HID)
#define NCTA   128
#define NTHR   128

// SMEM byte offsets
#define SO_W    0          // 131072 B : [plane hi/lo][tile 0..127][256 fp16]
#define SO_A    131072     // 2 stages x 16384 B (single fp16 plane)
#define SO_BIAS 163840     // 32 floats
#define SMEM_TOTAL 163968

// ---- persistent device scratch (no cudaMalloc allowed) ----
__device__ __align__(16) __half g_w[(size_t)NCTA*2*128*256];      // 16MB
__device__ __align__(16) __half g_x[(size_t)TSTEPS*32768];        // 32MB
__device__ __align__(16) __half g_h0[2*32768];
__device__ __align__(16) __half g_h1[2*32768];
__device__ unsigned g_bar;

// ---------------- helpers ----------------
__device__ __forceinline__ void cp_async16(void* sdst, const void* gsrc) {
    unsigned sa;
    asm("{ .reg .u64 t; cvta.to.shared.u64 t, %1; cvt.u32.u64 %0, t; }"
        : "=r"(sa) : "l"(sdst));
    asm volatile("cp.async.cg.shared.global [%0], [%1], 16;\n" :: "r"(sa), "l"(gsrc));
}
#define CP_COMMIT() asm volatile("cp.async.commit_group;\n")
#define CP_WAIT(n)  asm volatile("cp.async.wait_group %0;\n" :: "n"(n))

__device__ __forceinline__ void mma16816(float* d,
        uint32_t a0, uint32_t a1, uint32_t a2, uint32_t a3,
        uint32_t b0, uint32_t b1) {
    asm volatile(
      "mma.sync.aligned.m16n8k16.row.col.f32.f16.f16.f32 "
      "{%0,%1,%2,%3}, {%4,%5,%6,%7}, {%8,%9}, {%0,%1,%2,%3};"
      : "+f"(d[0]), "+f"(d[1]), "+f"(d[2]), "+f"(d[3])
      : "r"(a0), "r"(a1), "r"(a2), "r"(a3), "r"(b0), "r"(b1));
}

// fragment-order position of k-local element within a 16-wide act row
__device__ __host__ __forceinline__ int p_of_kl(int kl) {
    return ((kl & 7) >> 1) * 4 + ((kl >> 3) << 1) + (kl & 1);
}

// grid barrier (monotonic counter: safe across graph replays)
__device__ __forceinline__ void grid_sync() {
    __threadfence();
    __syncthreads();
    if (threadIdx.x == 0) {
        unsigned arrive = atomicAdd(&g_bar, 1u);
        unsigned target = (arrive / NCTA + 1u) * NCTA;
        while (*(volatile unsigned*)&g_bar < target) { }
        __threadfence();
    }
    __syncthreads();
}

// ---------------- prep kernels ----------------
// W fragment image per CTA: [plane hi/lo][tile ti = s*2+mb][lane L][8 fp16]
__global__ void prep_w(const float* __restrict__ Wx, const float* __restrict__ Wh) {
    const int blk = blockIdx.x;               // cta*8 + ch
    const int ch = blk & 7, cta = blk >> 3;
    const int layer = cta >> 6, hb = cta & 63;
    const float* wx = Wx + (size_t)layer * 2048 * 512;
    const float* wh = Wh + (size_t)layer * 2048 * 512;
    const size_t base_hi = ((size_t)cta * 2 + 0) * 128 * 256;
    const size_t base_lo = ((size_t)cta * 2 + 1) * 128 * 256;
    for (int e = threadIdx.x; e < 16 * 256; e += blockDim.x) {
        int ti  = ch * 16 + (e >> 8);
        int q16 = e & 255;
        int L = q16 >> 3, eb = q16 & 7;
        int qreg = eb >> 1, half = eb & 1;
        int s = ti >> 1, mb = ti & 1;
        int m  = (L >> 2) + ((qreg & 1) << 3) + (mb << 4);   // row 0..31
        int kl = ((L & 3) << 1) + ((qreg >> 1) << 3) + half;
        int k  = (s << 4) + kl;
        int R  = (m >> 3) * 512 + hb * 8 + (m & 7);
        float v = (k < 512) ? wx[(size_t)R * 512 + k]
                            : wh[(size_t)R * 512 + (k - 512)];
        __half hi = __float2half_rn(v);
        __half lo = __float2half_rn(v - __half2float(hi));
        size_t off = (size_t)ti * 256 + q16;
        g_w[base_hi + off] = hi;
        g_w[base_lo + off] = lo;
    }
}

// x fragment image: [t][s 0..31][n 0..63][16], k-local position p = p_of_kl(kl)
__global__ void prep_x(const float* __restrict__ x) {
    const int t = blockIdx.x;
    const float* src = x + (size_t)t * BH;
    const size_t dst = (size_t)t * 32768;
    for (int e = threadIdx.x; e < 32768; e += blockDim.x) {
        int s = e >> 10, n = (e >> 4) & 63, p = e & 15;
        int q = p >> 2, r = p & 3;
        int kl = (q << 1) + (r & 1) + ((r >> 1) << 3);
        g_x[dst + e] = __float2half_rn(src[n * 512 + ((s << 4) + kl)]);
    }
}

// ---------------- main persistent kernel ----------------
__global__ void __launch_bounds__(NTHR, 1)
lstm_mma(const float* __restrict__ bh, float* __restrict__ out)
{
    extern __shared__ __align__(16) char smem[];
    const int tid = threadIdx.x;
    const int L = tid & 31, warp = tid >> 5;
    const int cta = blockIdx.x, layer = cta >> 6, hb = cta & 63;

    // ---- resident weight load (once) ----
    {
        const char* wsrc = (const char*)(g_w + (size_t)cta * 65536);
        for (int i = tid; i < 8192; i += NTHR)
            cp_async16(smem + SO_W + i * 16, wsrc + i * 16);
        CP_COMMIT();
    }
    float* bias_s = (float*)(smem + SO_BIAS);
    if (tid < 32)
        bias_s[tid] = bh[layer * 2048 + (tid >> 3) * 512 + hb * 8 + (tid & 7)];
    CP_WAIT(0);
    __syncthreads();

    // epilogue constants
    const int j  = L >> 2;                 // hidden within CTA (0..7)
    const int hh = hb * 8 + j;             // global hidden index
    const int sH = hh >> 4;
    const int pH = p_of_kl(hh & 15);
    const float bi = bias_s[j],      bf = bias_s[8 + j];
    const float bg = bias_s[16 + j], bo = bias_s[24 + j];

    float c_st[4] = {0.f, 0.f, 0.f, 0.f};
    float h_st[4] = {0.f, 0.f, 0.f, 0.f};

    const int n0 = (warp << 4) + (L >> 2);   // act row for nb=0
    const char* wbase = smem + SO_W;

    for (int w = 0; w <= TSTEPS; ++w) {
        const bool active = (layer == 0) ? (w < TSTEPS) : (w >= 1);
        if (active) {
            const int t = (layer == 0) ? w : (w - 1);
            const int nch = (t == 0) ? 4 : 8;

            const __half *Asrc, *Bsrc;
            if (layer == 0) {
                Asrc = g_x + (size_t)t * 32768;
                Bsrc = g_h0 + ((t - 1) & 1) * 32768;
            } else {
                Asrc = g_h0 + (t & 1) * 32768;
                Bsrc = g_h1 + ((t - 1) & 1) * 32768;
            }

            float d[2][2][4];
            #pragma unroll
            for (int mb = 0; mb < 2; ++mb)
                #pragma unroll
                for (int nb = 0; nb < 2; ++nb)
                    #pragma unroll
                    for (int q = 0; q < 4; ++q) d[mb][nb][q] = 0.f;

            auto prefetch = [&](int c) {
                const int st = c & 1;
                const __half* s = (c < 4) ? Asrc + c * 8192 : Bsrc + (c - 4) * 8192;
                char* dst = smem + SO_A + st * 16384;
                #pragma unroll
                for (int i = 0; i < 8; ++i) {
                    int e = i * NTHR + tid;
                    cp_async16(dst + e * 16, (const char*)s + e * 16);
                }
                CP_COMMIT();
            };

            prefetch(0);
            for (int c = 0; c < nch; ++c) {
                if (c + 1 < nch) { prefetch(c + 1); CP_WAIT(1); }
                else             { CP_WAIT(0); }
                __syncthreads();

                const char* abase = smem + SO_A + (c & 1) * 16384;

                // fragment double buffer (one sl ahead)
                uint4 WH0[2], WH1[2], WL0[2], WL1[2];
                uint2 AH0[2], AH1[2];

                auto ldfrag = [&](int sl, int bufi) {
                    const int s2 = ((c << 3) + sl) << 1;
                    WH0[bufi] = *(const uint4*)(wbase + (size_t)(      s2    ) * 512 + L * 16);
                    WH1[bufi] = *(const uint4*)(wbase + (size_t)(      s2 + 1) * 512 + L * 16);
                    WL0[bufi] = *(const uint4*)(wbase + (size_t)(128 + s2    ) * 512 + L * 16);
                    WL1[bufi] = *(const uint4*)(wbase + (size_t)(128 + s2 + 1) * 512 + L * 16);
                    const int ro0 = ((sl << 6) + n0) * 32 + (L & 3) * 8;
                    AH0[bufi] = *(const uint2*)(abase + ro0);
                    AH1[bufi] = *(const uint2*)(abase + ro0 + 8 * 32);
                };

                ldfrag(0, 0);
                #pragma unroll
                for (int sl = 0; sl < 8; ++sl) {
                    const int cur = sl & 1;
                    if (sl < 7) ldfrag(sl + 1, cur ^ 1);

                    const uint4 wh0 = WH0[cur], wh1 = WH1[cur];
                    const uint4 wl0 = WL0[cur], wl1 = WL1[cur];
                    const uint2 ah0 = AH0[cur], ah1 = AH1[cur];

                    // interleaved: same-accumulator reuse distance = 4
                    mma16816(d[0][0], wh0.x, wh0.y, wh0.z, wh0.w, ah0.x, ah0.y);
                    mma16816(d[0][1], wh0.x, wh0.y, wh0.z, wh0.w, ah1.x, ah1.y);
                    mma16816(d[1][0], wh1.x, wh1.y, wh1.z, wh1.w, ah0.x, ah0.y);
                    mma16816(d[1][1], wh1.x, wh1.y, wh1.z, wh1.w, ah1.x, ah1.y);

                    mma16816(d[0][0], wl0.x, wl0.y, wl0.z, wl0.w, ah0.x, ah0.y);
                    mma16816(d[0][1], wl0.x, wl0.y, wl0.z, wl0.w, ah1.x, ah1.y);
                    mma16816(d[1][0], wl1.x, wl1.y, wl1.z, wl1.w, ah0.x, ah0.y);
                    mma16816(d[1][1], wl1.x, wl1.y, wl1.z, wl1.w, ah1.x, ah1.y);
                }
                __syncthreads();
            }

            // ---- epilogue: gates; republish h (frag order, single fp16) ----
            __half* dh = (layer ? g_h1 : g_h0) + (t & 1) * 32768;
            float* orow = out + (size_t)t * BH;
            #pragma unroll
            for (int nb = 0; nb < 2; ++nb) {
                #pragma unroll
                for (int cc = 0; cc < 2; ++cc) {
                    const int si = nb * 2 + cc;
                    const int b  = (warp << 4) + (nb << 3) + ((L & 3) << 1) + cc;
                    float pi = d[0][nb][cc]     + bi;
                    float pf = d[0][nb][2 + cc] + bf;
                    float pg = d[1][nb][cc]     + bg;
                    float po = d[1][nb][2 + cc] + bo;
                    float ig = __fdividef(1.f, 1.f + __expf(-pi));
                    float fg = __fdividef(1.f, 1.f + __expf(-pf));
                    float gt = 2.f * __fdividef(1.f, 1.f + __expf(-2.f * pg)) - 1.f;
                    float og = __fdividef(1.f, 1.f + __expf(-po));
                    float cn = fg * c_st[si] + ig * gt;
                    c_st[si] = cn;
                    float th = 2.f * __fdividef(1.f, 1.f + __expf(-2.f * cn)) - 1.f;
                    float hn = og * th;
                    h_st[si] = hn;
                    dh[sH * 1024 + b * 16 + pH] = __float2half_rn(hn);
                    if (layer == 1) orow[b * 512 + hh] = hn;
                }
            }
        }
        grid_sync();
    }

    // ---- final h, c tails: out layout = [out | h(L,B,H) | c(L,B,H)] ----
    const size_t base = (size_t)TSTEPS * BH;
    #pragma unroll
    for (int nb = 0; nb < 2; ++nb)
        #pragma unroll
        for (int cc = 0; cc < 2; ++cc) {
            const int si = nb * 2 + cc;
            const int b  = (warp << 4) + (nb << 3) + ((L & 3) << 1) + cc;
            out[base + (size_t)layer * BH + (size_t)b * 512 + hh] = h_st[si];
            out[base + 2 * (size_t)BH + (size_t)layer * BH + (size_t)b * 512 + hh] = c_st[si];
        }
}

extern "C" void kernel_launch(void* const* d_in, const int* in_sizes, int n_in,
                              void* d_out, int out_size) {
    (void)in_sizes; (void)n_in; (void)out_size;
    const float* x  = (const float*)d_in[0];
    const float* Wx = (const float*)d_in[1];
    const float* Wh = (const float*)d_in[2];
    const float* bh = (const float*)d_in[3];
    float* out = (float*)d_out;

    prep_w<<<NCTA * 8, 128>>>(Wx, Wh);
    prep_x<<<TSTEPS, 256>>>(x);

    cudaFuncSetAttribute(lstm_mma, cudaFuncAttributeMaxDynamicSharedMemorySize,
                         SMEM_TOTAL);
    lstm_mma<<<NCTA, NTHR, SMEM_TOTAL>>>(bh, out);
}

// round 11
// speedup vs baseline: 1.6754x; 1.2453x over previous
#include <cuda_runtime.h>
#include <cuda_fp16.h>
#include <cstdint>

// ---------------------------------------------------------------------------
// LSTM_41764261986630 : 2-layer LSTM, T=512, B=64, IN=H=512
// mma.sync (HMMA) single-term fp16 (W*A, fp32 accum), persistent,
// weight-stationary.  R10: 512 -> 256 MMAs/warp/wave and W LDS halved
// (drop W-lo plane; rel_err budget ~4.3e-4 vs 1e-3 threshold).
// Skeleton identical to R9 (fragment layouts, double-buffer, interleave).
// ---------------------------------------------------------------------------

#define TSTEPS 512
#define BATCH  64
#define HID    512
#define BH     (BATCH*HID)
#define NCTA   128
#define NTHR   128

// SMEM byte offsets
#define SO_W    0          // 65536 B : [tile 0..127][256 fp16]
#define SO_A    65536      // 2 stages x 16384 B (single fp16 plane)
#define SO_BIAS 98304      // 32 floats
#define SMEM_TOTAL 98432

// ---- persistent device scratch (no cudaMalloc allowed) ----
__device__ __align__(16) __half g_w[(size_t)NCTA*128*256];        // 8MB
__device__ __align__(16) __half g_x[(size_t)TSTEPS*32768];        // 32MB
__device__ __align__(16) __half g_h0[2*32768];
__device__ __align__(16) __half g_h1[2*32768];
__device__ unsigned g_bar;

// ---------------- helpers ----------------
__device__ __forceinline__ void cp_async16(void* sdst, const void* gsrc) {
    unsigned sa;
    asm("{ .reg .u64 t; cvta.to.shared.u64 t, %1; cvt.u32.u64 %0, t; }"
        : "=r"(sa) : "l"(sdst));
    asm volatile("cp.async.cg.shared.global [%0], [%1], 16;\n" :: "r"(sa), "l"(gsrc));
}
#define CP_COMMIT() asm volatile("cp.async.commit_group;\n")
#define CP_WAIT(n)  asm volatile("cp.async.wait_group %0;\n" :: "n"(n))

__device__ __forceinline__ void mma16816(float* d,
        uint32_t a0, uint32_t a1, uint32_t a2, uint32_t a3,
        uint32_t b0, uint32_t b1) {
    asm volatile(
      "mma.sync.aligned.m16n8k16.row.col.f32.f16.f16.f32 "
      "{%0,%1,%2,%3}, {%4,%5,%6,%7}, {%8,%9}, {%0,%1,%2,%3};"
      : "+f"(d[0]), "+f"(d[1]), "+f"(d[2]), "+f"(d[3])
      : "r"(a0), "r"(a1), "r"(a2), "r"(a3), "r"(b0), "r"(b1));
}

// fragment-order position of k-local element within a 16-wide act row
__device__ __host__ __forceinline__ int p_of_kl(int kl) {
    return ((kl & 7) >> 1) * 4 + ((kl >> 3) << 1) + (kl & 1);
}

// grid barrier (monotonic counter: safe across graph replays)
__device__ __forceinline__ void grid_sync() {
    __threadfence();
    __syncthreads();
    if (threadIdx.x == 0) {
        unsigned arrive = atomicAdd(&g_bar, 1u);
        unsigned target = (arrive / NCTA + 1u) * NCTA;
        while (*(volatile unsigned*)&g_bar < target) { }
        __threadfence();
    }
    __syncthreads();
}

// ---------------- prep kernels ----------------
// W fragment image per CTA: [tile ti = s*2+mb][lane L][8 fp16]
__global__ void prep_w(const float* __restrict__ Wx, const float* __restrict__ Wh) {
    const int blk = blockIdx.x;               // cta*8 + ch
    const int ch = blk & 7, cta = blk >> 3;
    const int layer = cta >> 6, hb = cta & 63;
    const float* wx = Wx + (size_t)layer * 2048 * 512;
    const float* wh = Wh + (size_t)layer * 2048 * 512;
    const size_t base = (size_t)cta * 128 * 256;
    for (int e = threadIdx.x; e < 16 * 256; e += blockDim.x) {
        int ti  = ch * 16 + (e >> 8);
        int q16 = e & 255;
        int L = q16 >> 3, eb = q16 & 7;
        int qreg = eb >> 1, half = eb & 1;
        int s = ti >> 1, mb = ti & 1;
        int m  = (L >> 2) + ((qreg & 1) << 3) + (mb << 4);   // row 0..31
        int kl = ((L & 3) << 1) + ((qreg >> 1) << 3) + half;
        int k  = (s << 4) + kl;
        int R  = (m >> 3) * 512 + hb * 8 + (m & 7);
        float v = (k < 512) ? wx[(size_t)R * 512 + k]
                            : wh[(size_t)R * 512 + (k - 512)];
        g_w[base + (size_t)ti * 256 + q16] = __float2half_rn(v);
    }
}

// x fragment image: [t][s 0..31][n 0..63][16], k-local position p = p_of_kl(kl)
__global__ void prep_x(const float* __restrict__ x) {
    const int t = blockIdx.x;
    const float* src = x + (size_t)t * BH;
    const size_t dst = (size_t)t * 32768;
    for (int e = threadIdx.x; e < 32768; e += blockDim.x) {
        int s = e >> 10, n = (e >> 4) & 63, p = e & 15;
        int q = p >> 2, r = p & 3;
        int kl = (q << 1) + (r & 1) + ((r >> 1) << 3);
        g_x[dst + e] = __float2half_rn(src[n * 512 + ((s << 4) + kl)]);
    }
}

// ---------------- main persistent kernel ----------------
__global__ void __launch_bounds__(NTHR, 1)
lstm_mma(const float* __restrict__ bh, float* __restrict__ out)
{
    extern __shared__ __align__(16) char smem[];
    const int tid = threadIdx.x;
    const int L = tid & 31, warp = tid >> 5;
    const int cta = blockIdx.x, layer = cta >> 6, hb = cta & 63;

    // ---- resident weight load (once) ----
    {
        const char* wsrc = (const char*)(g_w + (size_t)cta * 32768);
        for (int i = tid; i < 4096; i += NTHR)
            cp_async16(smem + SO_W + i * 16, wsrc + i * 16);
        CP_COMMIT();
    }
    float* bias_s = (float*)(smem + SO_BIAS);
    if (tid < 32)
        bias_s[tid] = bh[layer * 2048 + (tid >> 3) * 512 + hb * 8 + (tid & 7)];
    CP_WAIT(0);
    __syncthreads();

    // epilogue constants
    const int j  = L >> 2;                 // hidden within CTA (0..7)
    const int hh = hb * 8 + j;             // global hidden index
    const int sH = hh >> 4;
    const int pH = p_of_kl(hh & 15);
    const float bi = bias_s[j],      bf = bias_s[8 + j];
    const float bg = bias_s[16 + j], bo = bias_s[24 + j];

    float c_st[4] = {0.f, 0.f, 0.f, 0.f};
    float h_st[4] = {0.f, 0.f, 0.f, 0.f};

    const int n0 = (warp << 4) + (L >> 2);   // act row for nb=0
    const char* wbase = smem + SO_W;

    for (int w = 0; w <= TSTEPS; ++w) {
        const bool active = (layer == 0) ? (w < TSTEPS) : (w >= 1);
        if (active) {
            const int t = (layer == 0) ? w : (w - 1);
            const int nch = (t == 0) ? 4 : 8;

            const __half *Asrc, *Bsrc;
            if (layer == 0) {
                Asrc = g_x + (size_t)t * 32768;
                Bsrc = g_h0 + ((t - 1) & 1) * 32768;
            } else {
                Asrc = g_h0 + (t & 1) * 32768;
                Bsrc = g_h1 + ((t - 1) & 1) * 32768;
            }

            float d[2][2][4];
            #pragma unroll
            for (int mb = 0; mb < 2; ++mb)
                #pragma unroll
                for (int nb = 0; nb < 2; ++nb)
                    #pragma unroll
                    for (int q = 0; q < 4; ++q) d[mb][nb][q] = 0.f;

            auto prefetch = [&](int c) {
                const int st = c & 1;
                const __half* s = (c < 4) ? Asrc + c * 8192 : Bsrc + (c - 4) * 8192;
                char* dst = smem + SO_A + st * 16384;
                #pragma unroll
                for (int i = 0; i < 8; ++i) {
                    int e = i * NTHR + tid;
                    cp_async16(dst + e * 16, (const char*)s + e * 16);
                }
                CP_COMMIT();
            };

            prefetch(0);
            for (int c = 0; c < nch; ++c) {
                if (c + 1 < nch) { prefetch(c + 1); CP_WAIT(1); }
                else             { CP_WAIT(0); }
                __syncthreads();

                const char* abase = smem + SO_A + (c & 1) * 16384;

                // fragment double buffer (one sl ahead)
                uint4 WH0[2], WH1[2];
                uint2 AH0[2], AH1[2];

                auto ldfrag = [&](int sl, int bufi) {
                    const int s2 = ((c << 3) + sl) << 1;
                    WH0[bufi] = *(const uint4*)(wbase + (size_t)(s2    ) * 512 + L * 16);
                    WH1[bufi] = *(const uint4*)(wbase + (size_t)(s2 + 1) * 512 + L * 16);
                    const int ro0 = ((sl << 6) + n0) * 32 + (L & 3) * 8;
                    AH0[bufi] = *(const uint2*)(abase + ro0);
                    AH1[bufi] = *(const uint2*)(abase + ro0 + 8 * 32);
                };

                ldfrag(0, 0);
                #pragma unroll
                for (int sl = 0; sl < 8; ++sl) {
                    const int cur = sl & 1;
                    if (sl < 7) ldfrag(sl + 1, cur ^ 1);

                    const uint4 wh0 = WH0[cur], wh1 = WH1[cur];
                    const uint2 ah0 = AH0[cur], ah1 = AH1[cur];

                    // 4 independent accumulator chains
                    mma16816(d[0][0], wh0.x, wh0.y, wh0.z, wh0.w, ah0.x, ah0.y);
                    mma16816(d[0][1], wh0.x, wh0.y, wh0.z, wh0.w, ah1.x, ah1.y);
                    mma16816(d[1][0], wh1.x, wh1.y, wh1.z, wh1.w, ah0.x, ah0.y);
                    mma16816(d[1][1], wh1.x, wh1.y, wh1.z, wh1.w, ah1.x, ah1.y);
                }
                __syncthreads();
            }

            // ---- epilogue: gates; republish h (frag order, single fp16) ----
            __half* dh = (layer ? g_h1 : g_h0) + (t & 1) * 32768;
            float* orow = out + (size_t)t * BH;
            #pragma unroll
            for (int nb = 0; nb < 2; ++nb) {
                #pragma unroll
                for (int cc = 0; cc < 2; ++cc) {
                    const int si = nb * 2 + cc;
                    const int b  = (warp << 4) + (nb << 3) + ((L & 3) << 1) + cc;
                    float pi = d[0][nb][cc]     + bi;
                    float pf = d[0][nb][2 + cc] + bf;
                    float pg = d[1][nb][cc]     + bg;
                    float po = d[1][nb][2 + cc] + bo;
                    float ig = __fdividef(1.f, 1.f + __expf(-pi));
                    float fg = __fdividef(1.f, 1.f + __expf(-pf));
                    float gt = 2.f * __fdividef(1.f, 1.f + __expf(-2.f * pg)) - 1.f;
                    float og = __fdividef(1.f, 1.f + __expf(-po));
                    float cn = fg * c_st[si] + ig * gt;
                    c_st[si] = cn;
                    float th = 2.f * __fdividef(1.f, 1.f + __expf(-2.f * cn)) - 1.f;
                    float hn = og * th;
                    h_st[si] = hn;
                    dh[sH * 1024 + b * 16 + pH] = __float2half_rn(hn);
                    if (layer == 1) orow[b * 512 + hh] = hn;
                }
            }
        }
        grid_sync();
    }

    // ---- final h, c tails: out layout = [out | h(L,B,H) | c(L,B,H)] ----
    const size_t base = (size_t)TSTEPS * BH;
    #pragma unroll
    for (int nb = 0; nb < 2; ++nb)
        #pragma unroll
        for (int cc = 0; cc < 2; ++cc) {
            const int si = nb * 2 + cc;
            const int b  = (warp << 4) + (nb << 3) + ((L & 3) << 1) + cc;
            out[base + (size_t)layer * BH + (size_t)b * 512 + hh] = h_st[si];
            out[base + 2 * (size_t)BH + (size_t)layer * BH + (size_t)b * 512 + hh] = c_st[si];
        }
}

extern "C" void kernel_launch(void* const* d_in, const int* in_sizes, int n_in,
                              void* d_out, int out_size) {
    (void)in_sizes; (void)n_in; (void)out_size;
    const float* x  = (const float*)d_in[0];
    const float* Wx = (const float*)d_in[1];
    const float* Wh = (const float*)d_in[2];
    const float* bh = (const float*)d_in[3];
    float* out = (float*)d_out;

    prep_w<<<NCTA * 8, 128>>>(Wx, Wh);
    prep_x<<<TSTEPS, 256>>>(x);

    cudaFuncSetAttribute(lstm_mma, cudaFuncAttributeMaxDynamicSharedMemorySize,
                         SMEM_TOTAL);
    lstm_mma<<<NCTA, NTHR, SMEM_TOTAL>>>(bh, out);
}